// round 12
// baseline (speedup 1.0000x reference)
#include <cuda_runtime.h>
#include <cuda_bf16.h>
#include <stdint.h>

#define NMAX 50000
#define HH   128
#define EMAX 800000
#define CC   40

// ---------------- scratch ----------------
__device__ int   g_is32;
__device__ int   g_degi  [NMAX];
__device__ int   g_off   [NMAX + 1];
__device__ int   g_cursor[NMAX];
__device__ float g_dinv  [NMAX];
__device__ __align__(8) int2 g_edge[EMAX];      // (src, norm-bits) sorted by dst
__device__ __align__(16) float g_Whi[4 * HH * HH];
__device__ __align__(16) float g_Wlo[4 * HH * HH];
__device__ __align__(16) float g_H [NMAX * HH];
__device__ __align__(16) float g_X1[NMAX * HH];
__device__ __align__(16) float g_X2[NMAX * HH];

// ---------------- edge access ----------------
__device__ __forceinline__ int edge_src(const void* ei, int E, int e) {
    return g_is32 ? ((const int*)ei)[e] : (int)((const long long*)ei)[e];
}
__device__ __forceinline__ int edge_dst(const void* ei, int E, int e) {
    return g_is32 ? ((const int*)ei)[E + e] : (int)((const long long*)ei)[E + e];
}

// ---------------- tf32 split ----------------
__device__ __forceinline__ void split_tf32(float x, float& hi, float& lo) {
    uint32_t hb;
    asm("cvt.rna.tf32.f32 %0, %1;" : "=r"(hb) : "f"(x));
    hi = __uint_as_float(hb);
    float r = x - hi;
    uint32_t lb;
    asm("cvt.rna.tf32.f32 %0, %1;" : "=r"(lb) : "f"(r));
    lo = __uint_as_float(lb);
}

#define MMA_TF32(c, a, b) \
    asm volatile("mma.sync.aligned.m16n8k8.row.col.f32.tf32.tf32.f32 " \
        "{%0,%1,%2,%3}, {%4,%5,%6,%7}, {%8,%9}, {%0,%1,%2,%3};" \
        : "+f"((c)[0]), "+f"((c)[1]), "+f"((c)[2]), "+f"((c)[3]) \
        : "r"((a)[0]), "r"((a)[1]), "r"((a)[2]), "r"((a)[3]), \
          "r"((b)[0]), "r"((b)[1]))

// ---------------- CSR build ----------------
__global__ void init_k(const void* ei, int E, int n) {
    int i = blockIdx.x * blockDim.x + threadIdx.x;
    if (i < n) { g_degi[i] = 0; g_cursor[i] = 0; }
    if (blockIdx.x == 0 && threadIdx.x < 32) {
        const long long* p = (const long long*)ei;
        int lim = (E < 32) ? E : 32;
        long long v = (threadIdx.x < lim) ? p[threadIdx.x] : 0;
        unsigned bad = __ballot_sync(0xffffffffu, v < 0 || v >= (long long)n);
        if (threadIdx.x == 0) g_is32 = bad ? 1 : 0;
    }
}

// pre-split all 4 weight matrices into tf32 hi/lo planes
__global__ void split_w_k(const float* __restrict__ Ws) {
    int i = blockIdx.x * blockDim.x + threadIdx.x;
    if (i < 4 * HH * HH) {
        float hi, lo; split_tf32(Ws[i], hi, lo);
        g_Whi[i] = hi; g_Wlo[i] = lo;
    }
}

__global__ void hist_k(const void* ei, int E) {
    int e = blockIdx.x * blockDim.x + threadIdx.x;
    if (e < E) atomicAdd(&g_degi[edge_dst(ei, E, e)], 1);
}

__global__ void scan_k(int n) {
    __shared__ int shw[32];
    __shared__ int carry, btot;
    int tid = threadIdx.x, lane = tid & 31, wid = tid >> 5;
    if (tid == 0) carry = 0;
    __syncthreads();
    for (int base = 0; base < n; base += 1024) {
        int i = base + tid;
        int d = (i < n) ? g_degi[i] : 0;
        if (i < n) g_dinv[i] = rsqrtf((float)(d + 1));
        int incl = d;
        #pragma unroll
        for (int o = 1; o < 32; o <<= 1) {
            int v = __shfl_up_sync(0xffffffffu, incl, o);
            if (lane >= o) incl += v;
        }
        if (lane == 31) shw[wid] = incl;
        __syncthreads();
        if (wid == 0) {
            int w = shw[lane];
            int wi = w;
            #pragma unroll
            for (int o = 1; o < 32; o <<= 1) {
                int v = __shfl_up_sync(0xffffffffu, wi, o);
                if (lane >= o) wi += v;
            }
            shw[lane] = wi - w;
            if (lane == 31) btot = wi;
        }
        __syncthreads();
        if (i < n) g_off[i] = carry + shw[wid] + incl - d;
        __syncthreads();
        if (tid == 0) carry += btot;
        __syncthreads();
    }
    if (tid == 0) g_off[n] = carry;
}

__global__ void bucket_k(const void* ei, int E) {
    int e = blockIdx.x * blockDim.x + threadIdx.x;
    if (e >= E) return;
    int s = edge_src(ei, E, e);
    int d = edge_dst(ei, E, e);
    int pos = g_off[d] + atomicAdd(&g_cursor[d], 1);
    float w = g_dinv[s] * g_dinv[d];
    g_edge[pos] = make_int2(s, __float_as_int(w));
}

// ---------------- tensor-core GEMM, fragment-permuted smem ----------------
// block: 128 rows x 128 cols, 8 warps in 2(M) x 4(N); warp tile 64x32.
// smem layout (per 128x16 A chunk): As[(mtile*2+k8)*128 + lane*4 + vecidx]
//   vecidx: [0]=(gid,tig) [1]=(gid+8,tig) [2]=(gid,tig+4) [3]=(gid+8,tig+4)
// B chunk 16x128: Bs[(ntile*2+k8)*64 + lane*2 + khalf]  khalf: k=tig / k=tig+4
__global__ __launch_bounds__(256)
void gemm_tc_k(const float* __restrict__ Xin, int layer, int src_sel, int n) {
    const float* __restrict__ A = (src_sel == 0) ? Xin : (src_sel == 1 ? g_X1 : g_X2);
    const float* __restrict__ Whi = g_Whi + (size_t)layer * HH * HH;
    const float* __restrict__ Wlo = g_Wlo + (size_t)layer * HH * HH;
    float* __restrict__ C = g_H;

    __shared__ float As_hi[2048], As_lo[2048];
    __shared__ float Bs_hi[2048], Bs_lo[2048];

    const int tid  = threadIdx.x;
    const int lane = tid & 31, wid = tid >> 5;
    const int gid  = lane >> 2, tig = lane & 3;
    const int mtB  = (wid >> 2) * 4;   // mtile base (0 or 4)
    const int ntB  = (wid & 3) * 4;    // ntile base (0,4,8,12)
    const int row0 = blockIdx.x * 128;

    float acc[4][4][4] = {};

    for (int c16 = 0; c16 < HH; c16 += 16) {
        // ---- A tile 128x16: load + split + permuted scatter ----
        #pragma unroll
        for (int j = 0; j < 2; j++) {
            int idx = tid + j * 256;
            int r = idx >> 2, q = idx & 3;
            float4 v = make_float4(0.f, 0.f, 0.f, 0.f);
            if (row0 + r < n) v = *(const float4*)(A + (size_t)(row0 + r) * HH + c16 + q * 4);
            float xs[4] = {v.x, v.y, v.z, v.w};
            int mtile = r >> 4, rin = r & 15;
            int rg = rin & 7, rhalf = rin >> 3;
            #pragma unroll
            for (int u = 0; u < 4; u++) {
                int k = q * 4 + u;
                int k8 = k >> 3, ktig = k & 3, khalf = (k >> 2) & 1;
                int o = (mtile * 2 + k8) * 128 + (rg * 4 + ktig) * 4 + khalf * 2 + rhalf;
                float hi, lo; split_tf32(xs[u], hi, lo);
                As_hi[o] = hi; As_lo[o] = lo;
            }
        }
        // ---- W tile 16x128: pre-split, permuted scatter ----
        #pragma unroll
        for (int j = 0; j < 2; j++) {
            int idx = tid + j * 256;
            int kr = idx >> 5, cq = idx & 31;
            const float* ph = Whi + (size_t)(c16 + kr) * HH + cq * 4;
            const float* pl = Wlo + (size_t)(c16 + kr) * HH + cq * 4;
            float4 vh = *(const float4*)ph;
            float4 vl = *(const float4*)pl;
            float hs[4] = {vh.x, vh.y, vh.z, vh.w};
            float ls[4] = {vl.x, vl.y, vl.z, vl.w};
            int k8 = kr >> 3, ktig = kr & 3, khalf = (kr >> 2) & 1;
            #pragma unroll
            for (int u = 0; u < 4; u++) {
                int c = cq * 4 + u;
                int ntile = c >> 3, cg = c & 7;
                int o = (ntile * 2 + k8) * 64 + (cg * 4 + ktig) * 2 + khalf;
                Bs_hi[o] = hs[u]; Bs_lo[o] = ls[u];
            }
        }
        __syncthreads();

        #pragma unroll
        for (int ks = 0; ks < 2; ks++) {
            uint32_t bh[4][2], bl[4][2];
            #pragma unroll
            for (int nt = 0; nt < 4; nt++) {
                float2 h2 = *(const float2*)&Bs_hi[((ntB + nt) * 2 + ks) * 64 + lane * 2];
                float2 l2 = *(const float2*)&Bs_lo[((ntB + nt) * 2 + ks) * 64 + lane * 2];
                bh[nt][0] = __float_as_uint(h2.x); bh[nt][1] = __float_as_uint(h2.y);
                bl[nt][0] = __float_as_uint(l2.x); bl[nt][1] = __float_as_uint(l2.y);
            }
            #pragma unroll
            for (int mt = 0; mt < 4; mt++) {
                float4 a4h = *(const float4*)&As_hi[((mtB + mt) * 2 + ks) * 128 + lane * 4];
                float4 a4l = *(const float4*)&As_lo[((mtB + mt) * 2 + ks) * 128 + lane * 4];
                uint32_t ah[4] = {__float_as_uint(a4h.x), __float_as_uint(a4h.y),
                                  __float_as_uint(a4h.z), __float_as_uint(a4h.w)};
                uint32_t al[4] = {__float_as_uint(a4l.x), __float_as_uint(a4l.y),
                                  __float_as_uint(a4l.z), __float_as_uint(a4l.w)};
                #pragma unroll
                for (int nt = 0; nt < 4; nt++) {
                    MMA_TF32(acc[mt][nt], ah, bh[nt]);
                    MMA_TF32(acc[mt][nt], ah, bl[nt]);
                    MMA_TF32(acc[mt][nt], al, bh[nt]);
                }
            }
        }
        __syncthreads();
    }

    #pragma unroll
    for (int mt = 0; mt < 4; mt++) {
        #pragma unroll
        for (int nt = 0; nt < 4; nt++) {
            int r  = row0 + (mtB + mt) * 16 + gid;
            int cc = (ntB + nt) * 8 + tig * 2;
            if (r < n)
                *(float2*)(C + (size_t)r * HH + cc) =
                    make_float2(acc[mt][nt][0], acc[mt][nt][1]);
            if (r + 8 < n)
                *(float2*)(C + (size_t)(r + 8) * HH + cc) =
                    make_float2(acc[mt][nt][2], acc[mt][nt][3]);
        }
    }
}

// ---------------- fused aggregate + self-loop + bias + act + residual ----------------
template<int RELU, int RES>
__global__ __launch_bounds__(256)
void agg_k(const float* __restrict__ b, const float* __restrict__ rw,
           int out_sel, int n) {
    float* __restrict__ Xout = out_sel ? g_X2 : g_X1;
    const float* __restrict__ Xres = out_sel ? g_X1 : g_X2;
    const float* __restrict__ H = g_H;

    int node = blockIdx.x * (blockDim.x >> 5) + (threadIdx.x >> 5);
    if (node >= n) return;
    int lane = threadIdx.x & 31;
    int beg = __ldg(&g_off[node]);
    int end = __ldg(&g_off[node + 1]);

    float ax = 0.f, ay = 0.f, az = 0.f, aw = 0.f;
    int e = beg;
    for (; e + 1 < end; e += 2) {
        int2 e0 = __ldg(&g_edge[e]);
        int2 e1 = __ldg(&g_edge[e + 1]);
        float w0 = __int_as_float(e0.y);
        float w1 = __int_as_float(e1.y);
        float4 v0 = *(const float4*)(H + (size_t)e0.x * HH + lane * 4);
        float4 v1 = *(const float4*)(H + (size_t)e1.x * HH + lane * 4);
        ax += w0 * v0.x + w1 * v1.x;
        ay += w0 * v0.y + w1 * v1.y;
        az += w0 * v0.z + w1 * v1.z;
        aw += w0 * v0.w + w1 * v1.w;
    }
    if (e < end) {
        int2 e0 = __ldg(&g_edge[e]);
        float w0 = __int_as_float(e0.y);
        float4 v0 = *(const float4*)(H + (size_t)e0.x * HH + lane * 4);
        ax += w0 * v0.x; ay += w0 * v0.y; az += w0 * v0.z; aw += w0 * v0.w;
    }

    float dv = __ldg(&g_dinv[node]);
    float sn = dv * dv;
    float4 h  = *(const float4*)(H + (size_t)node * HH + lane * 4);
    float4 bb = *(const float4*)(b + lane * 4);
    float vx = ax + sn * h.x + bb.x;
    float vy = ay + sn * h.y + bb.y;
    float vz = az + sn * h.z + bb.z;
    float vw = aw + sn * h.w + bb.w;
    if (RELU) {
        vx = fmaxf(vx, 0.f); vy = fmaxf(vy, 0.f);
        vz = fmaxf(vz, 0.f); vw = fmaxf(vw, 0.f);
    }
    if (RES) {
        float w = *rw;
        float4 r = *(const float4*)(Xres + (size_t)node * HH + lane * 4);
        vx += w * r.x; vy += w * r.y; vz += w * r.z; vw += w * r.w;
    }
    *(float4*)(Xout + (size_t)node * HH + lane * 4) = make_float4(vx, vy, vz, vw);
}

// ---------------- head ----------------
__global__ void head_k(const float* __restrict__ W, const float* __restrict__ b,
                       float* __restrict__ out, int n) {
    int idx = blockIdx.x * blockDim.x + threadIdx.x;
    if (idx >= n * CC) return;
    int node = idx / CC;
    int c    = idx % CC;
    const float* xr = g_X2 + (size_t)node * HH;
    float a0 = 0.f, a1 = 0.f, a2 = 0.f, a3 = 0.f;
    #pragma unroll
    for (int k = 0; k < HH; k += 4) {
        a0 += xr[k + 0] * __ldg(W + (k + 0) * CC + c);
        a1 += xr[k + 1] * __ldg(W + (k + 1) * CC + c);
        a2 += xr[k + 2] * __ldg(W + (k + 2) * CC + c);
        a3 += xr[k + 3] * __ldg(W + (k + 3) * CC + c);
    }
    out[idx] = (a0 + a1) + (a2 + a3) + b[c];
}

// ---------------- launch ----------------
extern "C" void kernel_launch(void* const* d_in, const int* in_sizes, int n_in,
                              void* d_out, int out_size) {
    const float* X    = (const float*)d_in[0];
    const void*  ei   = d_in[1];
    const float* Ws   = (const float*)d_in[2];
    const float* bs   = (const float*)d_in[3];
    const float* mlpW = (const float*)d_in[4];
    const float* mlpb = (const float*)d_in[5];
    const float* rw   = (const float*)d_in[6];
    float* out = (float*)d_out;

    int n = in_sizes[0] / HH;
    int E = in_sizes[1] / 2;

    const int T = 256;

    init_k   <<<(n + T - 1) / T, T>>>(ei, E, n);
    split_w_k<<<(4 * HH * HH + T - 1) / T, T>>>(Ws);
    hist_k   <<<(E + T - 1) / T, T>>>(ei, E);
    scan_k   <<<1, 1024>>>(n);
    bucket_k <<<(E + T - 1) / T, T>>>(ei, E);

    int gblocks = (n + 127) / 128;
    int ablocks = (n + 7) / 8;

    gemm_tc_k<<<gblocks, T>>>(X, 0, 0, n);
    agg_k<1, 0><<<ablocks, T>>>(bs + 0 * HH, rw, 0, n);
    gemm_tc_k<<<gblocks, T>>>(X, 1, 1, n);
    agg_k<1, 1><<<ablocks, T>>>(bs + 1 * HH, rw, 1, n);
    gemm_tc_k<<<gblocks, T>>>(X, 2, 2, n);
    agg_k<1, 1><<<ablocks, T>>>(bs + 2 * HH, rw, 0, n);
    gemm_tc_k<<<gblocks, T>>>(X, 3, 1, n);
    agg_k<0, 0><<<ablocks, T>>>(bs + 3 * HH, rw, 1, n);

    head_k<<<(n * CC + T - 1) / T, T>>>(mlpW, mlpb, out, n);
}

// round 14
// speedup vs baseline: 1.5780x; 1.5780x over previous
#include <cuda_runtime.h>
#include <cuda_bf16.h>
#include <stdint.h>

#define NMAX 50000
#define HH   128
#define EMAX 800000
#define CC   40
#define SCAN_CHUNK 1024   // elements per scan block

// ---------------- scratch ----------------
__device__ int   g_is32;
__device__ int   g_degi  [NMAX];
__device__ int   g_off   [NMAX + 1];
__device__ int   g_cursor[NMAX];
__device__ float g_dinv  [NMAX];
__device__ int   g_bsum  [(NMAX + SCAN_CHUNK - 1) / SCAN_CHUNK];
__device__ int   g_bbase [(NMAX + SCAN_CHUNK - 1) / SCAN_CHUNK + 1];
__device__ __align__(8) int2 g_edge[EMAX];      // (src, norm-bits) sorted by dst
__device__ __align__(16) float g_H [NMAX * HH];
__device__ __align__(16) float g_X1[NMAX * HH];
__device__ __align__(16) float g_X2[NMAX * HH];

// ---------------- edge access ----------------
__device__ __forceinline__ int edge_src(const void* ei, int E, int e) {
    return g_is32 ? ((const int*)ei)[e] : (int)((const long long*)ei)[e];
}
__device__ __forceinline__ int edge_dst(const void* ei, int E, int e) {
    return g_is32 ? ((const int*)ei)[E + e] : (int)((const long long*)ei)[E + e];
}

// ---------------- CSR build ----------------
__global__ void init_k(const void* ei, int E, int n) {
    int i = blockIdx.x * blockDim.x + threadIdx.x;
    if (i < n) { g_degi[i] = 0; g_cursor[i] = 0; }
    if (blockIdx.x == 0 && threadIdx.x < 32) {
        const long long* p = (const long long*)ei;
        int lim = (E < 32) ? E : 32;
        long long v = (threadIdx.x < lim) ? p[threadIdx.x] : 0;
        unsigned bad = __ballot_sync(0xffffffffu, v < 0 || v >= (long long)n);
        if (threadIdx.x == 0) g_is32 = bad ? 1 : 0;
    }
}

__global__ void hist_k(const void* ei, int E) {
    int e = blockIdx.x * blockDim.x + threadIdx.x;
    if (e < E) atomicAdd(&g_degi[edge_dst(ei, E, e)], 1);
}

// phase 1: per-block degree sums (each block covers SCAN_CHUNK elements)
__global__ void bsum_k(int n) {
    __shared__ int sw[8];
    int tid = threadIdx.x, lane = tid & 31, wid = tid >> 5;
    int idx = blockIdx.x * SCAN_CHUNK + tid * 4;
    int s = 0;
    if (idx + 3 < n) {
        int4 d = *(const int4*)&g_degi[idx];
        s = d.x + d.y + d.z + d.w;
    } else {
        for (int j = 0; j < 4; j++) if (idx + j < n) s += g_degi[idx + j];
    }
    #pragma unroll
    for (int o = 16; o > 0; o >>= 1) s += __shfl_down_sync(0xffffffffu, s, o);
    if (lane == 0) sw[wid] = s;
    __syncthreads();
    if (wid == 0) {
        int v = (lane < 8) ? sw[lane] : 0;
        #pragma unroll
        for (int o = 4; o > 0; o >>= 1) v += __shfl_down_sync(0xffffffffu, v, o);
        if (lane == 0) g_bsum[blockIdx.x] = v;
    }
}

// phase 2: one warp scans the block sums (B <= 49)
__global__ void bscan_k(int B) {
    if (threadIdx.x >= 32) return;
    int lane = threadIdx.x;
    int carry = 0;
    for (int base = 0; base < B; base += 32) {
        int v = (base + lane < B) ? g_bsum[base + lane] : 0;
        int incl = v;
        #pragma unroll
        for (int o = 1; o < 32; o <<= 1) {
            int t = __shfl_up_sync(0xffffffffu, incl, o);
            if (lane >= o) incl += t;
        }
        if (base + lane < B) g_bbase[base + lane] = carry + incl - v;
        carry += __shfl_sync(0xffffffffu, incl, 31);
    }
    if (lane == 0) g_bbase[B] = carry;
}

// phase 3: intra-block exclusive scan + write offsets + dinv
__global__ void offs_k(int n, int B) {
    __shared__ int sw[8];
    int tid = threadIdx.x, lane = tid & 31, wid = tid >> 5;
    int idx = blockIdx.x * SCAN_CHUNK + tid * 4;
    int d0 = 0, d1 = 0, d2 = 0, d3 = 0;
    if (idx + 3 < n) {
        int4 d = *(const int4*)&g_degi[idx];
        d0 = d.x; d1 = d.y; d2 = d.z; d3 = d.w;
    } else {
        if (idx + 0 < n) d0 = g_degi[idx + 0];
        if (idx + 1 < n) d1 = g_degi[idx + 1];
        if (idx + 2 < n) d2 = g_degi[idx + 2];
        if (idx + 3 < n) d3 = g_degi[idx + 3];
    }
    int ls = d0 + d1 + d2 + d3;
    int incl = ls;
    #pragma unroll
    for (int o = 1; o < 32; o <<= 1) {
        int t = __shfl_up_sync(0xffffffffu, incl, o);
        if (lane >= o) incl += t;
    }
    if (lane == 31) sw[wid] = incl;
    __syncthreads();
    if (wid == 0) {
        int v = (lane < 8) ? sw[lane] : 0;
        int vi = v;
        #pragma unroll
        for (int o = 1; o < 8; o <<= 1) {
            int t = __shfl_up_sync(0xffffffffu, vi, o);
            if (lane >= o) vi += t;
        }
        if (lane < 8) sw[lane] = vi - v;
    }
    __syncthreads();
    int excl = g_bbase[blockIdx.x] + sw[wid] + incl - ls;
    if (idx + 0 < n) { g_off[idx + 0] = excl;                g_dinv[idx + 0] = rsqrtf((float)(d0 + 1)); }
    if (idx + 1 < n) { g_off[idx + 1] = excl + d0;           g_dinv[idx + 1] = rsqrtf((float)(d1 + 1)); }
    if (idx + 2 < n) { g_off[idx + 2] = excl + d0 + d1;      g_dinv[idx + 2] = rsqrtf((float)(d2 + 1)); }
    if (idx + 3 < n) { g_off[idx + 3] = excl + d0 + d1 + d2; g_dinv[idx + 3] = rsqrtf((float)(d3 + 1)); }
    if (blockIdx.x == 0 && tid == 0) g_off[n] = g_bbase[B];
}

__global__ void bucket_k(const void* ei, int E) {
    int e = blockIdx.x * blockDim.x + threadIdx.x;
    if (e >= E) return;
    int s = edge_src(ei, E, e);
    int d = edge_dst(ei, E, e);
    int pos = g_off[d] + atomicAdd(&g_cursor[d], 1);
    float w = g_dinv[s] * g_dinv[d];
    g_edge[pos] = make_int2(s, __float_as_int(w));
}

// ---------------- GEMM (SIMT, best measured): g_H[n,128] = src @ W ----------------
__global__ __launch_bounds__(256, 2)
void gemm128_k(const float* __restrict__ Xin, const float* __restrict__ W,
               int src_sel, int n) {
    const float* __restrict__ A = (src_sel == 0) ? Xin : (src_sel == 1 ? g_X1 : g_X2);
    float* __restrict__ C = g_H;

    __shared__ __align__(16) float As[32][132];
    __shared__ __align__(16) float Bs[32][128];
    const int tid  = threadIdx.x;
    const int row0 = blockIdx.x * 128;
    const int tm   = (tid >> 4) * 8;
    const int c0   = (tid & 15) * 4;

    float acc0[8][4] = {};
    float acc1[8][4] = {};

    for (int k0 = 0; k0 < HH; k0 += 32) {
        #pragma unroll
        for (int j = 0; j < 4; j++) {
            int t  = tid + j * 256;
            int r  = t >> 3;
            int kq = t & 7;
            float4 v = make_float4(0.f, 0.f, 0.f, 0.f);
            int grow = row0 + r;
            if (grow < n) v = *(const float4*)(A + (size_t)grow * HH + k0 + kq * 4);
            As[kq * 4 + 0][r] = v.x;
            As[kq * 4 + 1][r] = v.y;
            As[kq * 4 + 2][r] = v.z;
            As[kq * 4 + 3][r] = v.w;
        }
        #pragma unroll
        for (int j = 0; j < 4; j++) {
            int t  = tid + j * 256;
            int kr = t >> 5;
            int cq = t & 31;
            *(float4*)&Bs[kr][cq * 4] = *(const float4*)(W + (size_t)(k0 + kr) * HH + cq * 4);
        }
        __syncthreads();

        #pragma unroll
        for (int k = 0; k < 32; k++) {
            float4 b0 = *(const float4*)&Bs[k][c0];
            float4 b1 = *(const float4*)&Bs[k][c0 + 64];
            float4 a0 = *(const float4*)&As[k][tm];
            float4 a1 = *(const float4*)&As[k][tm + 4];
            float a[8] = {a0.x, a0.y, a0.z, a0.w, a1.x, a1.y, a1.z, a1.w};
            #pragma unroll
            for (int r = 0; r < 8; r++) {
                acc0[r][0] += a[r] * b0.x; acc0[r][1] += a[r] * b0.y;
                acc0[r][2] += a[r] * b0.z; acc0[r][3] += a[r] * b0.w;
                acc1[r][0] += a[r] * b1.x; acc1[r][1] += a[r] * b1.y;
                acc1[r][2] += a[r] * b1.z; acc1[r][3] += a[r] * b1.w;
            }
        }
        __syncthreads();
    }

    #pragma unroll
    for (int r = 0; r < 8; r++) {
        int grow = row0 + tm + r;
        if (grow < n) {
            *(float4*)(C + (size_t)grow * HH + c0) =
                make_float4(acc0[r][0], acc0[r][1], acc0[r][2], acc0[r][3]);
            *(float4*)(C + (size_t)grow * HH + c0 + 64) =
                make_float4(acc1[r][0], acc1[r][1], acc1[r][2], acc1[r][3]);
        }
    }
}

// ---------------- fused aggregate + self-loop + bias + act + residual ----------------
template<int RELU, int RES>
__global__ __launch_bounds__(256)
void agg_k(const float* __restrict__ b, const float* __restrict__ rw,
           int out_sel, int n) {
    float* __restrict__ Xout = out_sel ? g_X2 : g_X1;
    const float* __restrict__ Xres = out_sel ? g_X1 : g_X2;
    const float* __restrict__ H = g_H;

    int node = blockIdx.x * (blockDim.x >> 5) + (threadIdx.x >> 5);
    if (node >= n) return;
    int lane = threadIdx.x & 31;
    int beg = __ldg(&g_off[node]);
    int end = __ldg(&g_off[node + 1]);

    float ax = 0.f, ay = 0.f, az = 0.f, aw = 0.f;
    int e = beg;
    for (; e + 1 < end; e += 2) {
        int2 e0 = __ldg(&g_edge[e]);
        int2 e1 = __ldg(&g_edge[e + 1]);
        float w0 = __int_as_float(e0.y);
        float w1 = __int_as_float(e1.y);
        float4 v0 = *(const float4*)(H + (size_t)e0.x * HH + lane * 4);
        float4 v1 = *(const float4*)(H + (size_t)e1.x * HH + lane * 4);
        ax += w0 * v0.x + w1 * v1.x;
        ay += w0 * v0.y + w1 * v1.y;
        az += w0 * v0.z + w1 * v1.z;
        aw += w0 * v0.w + w1 * v1.w;
    }
    if (e < end) {
        int2 e0 = __ldg(&g_edge[e]);
        float w0 = __int_as_float(e0.y);
        float4 v0 = *(const float4*)(H + (size_t)e0.x * HH + lane * 4);
        ax += w0 * v0.x; ay += w0 * v0.y; az += w0 * v0.z; aw += w0 * v0.w;
    }

    float dv = __ldg(&g_dinv[node]);
    float sn = dv * dv;
    float4 h  = *(const float4*)(H + (size_t)node * HH + lane * 4);
    float4 bb = *(const float4*)(b + lane * 4);
    float vx = ax + sn * h.x + bb.x;
    float vy = ay + sn * h.y + bb.y;
    float vz = az + sn * h.z + bb.z;
    float vw = aw + sn * h.w + bb.w;
    if (RELU) {
        vx = fmaxf(vx, 0.f); vy = fmaxf(vy, 0.f);
        vz = fmaxf(vz, 0.f); vw = fmaxf(vw, 0.f);
    }
    if (RES) {
        float w = *rw;
        float4 r = *(const float4*)(Xres + (size_t)node * HH + lane * 4);
        vx += w * r.x; vy += w * r.y; vz += w * r.z; vw += w * r.w;
    }
    *(float4*)(Xout + (size_t)node * HH + lane * 4) = make_float4(vx, vy, vz, vw);
}

// ---------------- head ----------------
__global__ void head_k(const float* __restrict__ W, const float* __restrict__ b,
                       float* __restrict__ out, int n) {
    int idx = blockIdx.x * blockDim.x + threadIdx.x;
    if (idx >= n * CC) return;
    int node = idx / CC;
    int c    = idx % CC;
    const float* xr = g_X2 + (size_t)node * HH;
    float a0 = 0.f, a1 = 0.f, a2 = 0.f, a3 = 0.f;
    #pragma unroll
    for (int k = 0; k < HH; k += 4) {
        a0 += xr[k + 0] * __ldg(W + (k + 0) * CC + c);
        a1 += xr[k + 1] * __ldg(W + (k + 1) * CC + c);
        a2 += xr[k + 2] * __ldg(W + (k + 2) * CC + c);
        a3 += xr[k + 3] * __ldg(W + (k + 3) * CC + c);
    }
    out[idx] = (a0 + a1) + (a2 + a3) + b[c];
}

// ---------------- launch ----------------
extern "C" void kernel_launch(void* const* d_in, const int* in_sizes, int n_in,
                              void* d_out, int out_size) {
    const float* X    = (const float*)d_in[0];
    const void*  ei   = d_in[1];
    const float* Ws   = (const float*)d_in[2];
    const float* bs   = (const float*)d_in[3];
    const float* mlpW = (const float*)d_in[4];
    const float* mlpb = (const float*)d_in[5];
    const float* rw   = (const float*)d_in[6];
    float* out = (float*)d_out;

    int n = in_sizes[0] / HH;
    int E = in_sizes[1] / 2;

    const int T = 256;
    int B = (n + SCAN_CHUNK - 1) / SCAN_CHUNK;

    init_k <<<(n + T - 1) / T, T>>>(ei, E, n);
    hist_k <<<(E + T - 1) / T, T>>>(ei, E);
    bsum_k <<<B, 256>>>(n);
    bscan_k<<<1, 32>>>(B);
    offs_k <<<B, 256>>>(n, B);
    bucket_k<<<(E + T - 1) / T, T>>>(ei, E);

    int gblocks = (n + 127) / 128;
    int ablocks = (n + 7) / 8;

    gemm128_k<<<gblocks, T>>>(X, Ws + 0 * HH * HH, 0, n);
    agg_k<1, 0><<<ablocks, T>>>(bs + 0 * HH, rw, 0, n);
    gemm128_k<<<gblocks, T>>>(X, Ws + 1 * HH * HH, 1, n);
    agg_k<1, 1><<<ablocks, T>>>(bs + 1 * HH, rw, 1, n);
    gemm128_k<<<gblocks, T>>>(X, Ws + 2 * HH * HH, 2, n);
    agg_k<1, 1><<<ablocks, T>>>(bs + 2 * HH, rw, 0, n);
    gemm128_k<<<gblocks, T>>>(X, Ws + 3 * HH * HH, 1, n);
    agg_k<0, 0><<<ablocks, T>>>(bs + 3 * HH, rw, 1, n);

    head_k<<<(n * CC + T - 1) / T, T>>>(mlpW, mlpb, out, n);
}

// round 15
// speedup vs baseline: 2.0063x; 1.2714x over previous
#include <cuda_runtime.h>
#include <cuda_bf16.h>
#include <stdint.h>

#define NMAX 50000
#define HH   128
#define EMAX 800000
#define CC   40
#define SCAN_CHUNK 1024
#define ASTRIDE 72     // b16 units per A-smem row (64 + 8 pad); 144B = 9*16 ✓ ldmatrix-aligned

// ---------------- scratch ----------------
__device__ int   g_is32;
__device__ int   g_degi  [NMAX];
__device__ int   g_off   [NMAX + 1];
__device__ int   g_cursor[NMAX];
__device__ float g_dinv  [NMAX];
__device__ int   g_bsum  [(NMAX + SCAN_CHUNK - 1) / SCAN_CHUNK];
__device__ int   g_bbase [(NMAX + SCAN_CHUNK - 1) / SCAN_CHUNK + 1];
__device__ __align__(8) int2 g_edge[EMAX];
__device__ __align__(16) uint4 g_wfrag[4 * 8 * 16 * 32];  // [layer][k16chunk][n8grp][lane]
__device__ __align__(16) float g_H [NMAX * HH];
__device__ __align__(16) float g_X1[NMAX * HH];
__device__ __align__(16) float g_X2[NMAX * HH];

// ---------------- helpers ----------------
__device__ __forceinline__ int edge_src(const void* ei, int E, int e) {
    return g_is32 ? ((const int*)ei)[e] : (int)((const long long*)ei)[e];
}
__device__ __forceinline__ int edge_dst(const void* ei, int E, int e) {
    return g_is32 ? ((const int*)ei)[E + e] : (int)((const long long*)ei)[E + e];
}

__device__ __forceinline__ uint32_t pack_bf(float a, float b) {
    __nv_bfloat162 t = __floats2bfloat162_rn(a, b);   // .x=a low half, .y=b high half
    return *(uint32_t*)&t;
}
__device__ __forceinline__ void bsplit(float x, float& hi, float& lo) {
    __nv_bfloat16 h = __float2bfloat16_rn(x);
    hi = __bfloat162float(h);
    lo = x - hi;
}

#define MMA_BF16(c, a, b0, b1) \
    asm volatile("mma.sync.aligned.m16n8k16.row.col.f32.bf16.bf16.f32 " \
        "{%0,%1,%2,%3},{%4,%5,%6,%7},{%8,%9},{%0,%1,%2,%3};" \
        : "+f"((c)[0]), "+f"((c)[1]), "+f"((c)[2]), "+f"((c)[3]) \
        : "r"((a)[0]), "r"((a)[1]), "r"((a)[2]), "r"((a)[3]), "r"(b0), "r"(b1))

#define LDSM4(r, addr) \
    asm volatile("ldmatrix.sync.aligned.m8n8.x4.shared.b16 {%0,%1,%2,%3}, [%4];" \
        : "=r"((r)[0]), "=r"((r)[1]), "=r"((r)[2]), "=r"((r)[3]) : "r"(addr))

// ---------------- CSR build ----------------
__global__ void init_k(const void* ei, int E, int n) {
    int i = blockIdx.x * blockDim.x + threadIdx.x;
    if (i < n) { g_degi[i] = 0; g_cursor[i] = 0; }
    if (blockIdx.x == 0 && threadIdx.x < 32) {
        const long long* p = (const long long*)ei;
        int lim = (E < 32) ? E : 32;
        long long v = (threadIdx.x < lim) ? p[threadIdx.x] : 0;
        unsigned bad = __ballot_sync(0xffffffffu, v < 0 || v >= (long long)n);
        if (threadIdx.x == 0) g_is32 = bad ? 1 : 0;
    }
}

// pre-convert W into mma B-fragment order: for m16n8k16, lane l holds
// b0 = {B[kb][n], B[kb+1][n]}, b1 = {B[kb+8][n], B[kb+9][n]}, kb=(l&3)*2, n=grp*8+(l>>2)
__global__ void wfrag_k(const float* __restrict__ Ws) {
    int i = blockIdx.x * blockDim.x + threadIdx.x;
    if (i >= 4 * 8 * 16 * 32) return;
    int l = i & 31, g = (i >> 5) & 15, c = (i >> 9) & 7, layer = i >> 12;
    int nn = g * 8 + (l >> 2);
    int kb = c * 16 + (l & 3) * 2;
    const float* W = Ws + (size_t)layer * HH * HH;
    float w0 = W[(kb + 0) * HH + nn], w1 = W[(kb + 1) * HH + nn];
    float w2 = W[(kb + 8) * HH + nn], w3 = W[(kb + 9) * HH + nn];
    float h0, l0, h1, l1, h2, l2, h3, l3;
    bsplit(w0, h0, l0); bsplit(w1, h1, l1); bsplit(w2, h2, l2); bsplit(w3, h3, l3);
    uint4 o;
    o.x = pack_bf(h0, h1); o.y = pack_bf(h2, h3);
    o.z = pack_bf(l0, l1); o.w = pack_bf(l2, l3);
    g_wfrag[i] = o;
}

__global__ void hist_k(const void* ei, int E) {
    int e = blockIdx.x * blockDim.x + threadIdx.x;
    if (e < E) atomicAdd(&g_degi[edge_dst(ei, E, e)], 1);
}

__global__ void bsum_k(int n) {
    __shared__ int sw[8];
    int tid = threadIdx.x, lane = tid & 31, wid = tid >> 5;
    int idx = blockIdx.x * SCAN_CHUNK + tid * 4;
    int s = 0;
    if (idx + 3 < n) {
        int4 d = *(const int4*)&g_degi[idx];
        s = d.x + d.y + d.z + d.w;
    } else {
        for (int j = 0; j < 4; j++) if (idx + j < n) s += g_degi[idx + j];
    }
    #pragma unroll
    for (int o = 16; o > 0; o >>= 1) s += __shfl_down_sync(0xffffffffu, s, o);
    if (lane == 0) sw[wid] = s;
    __syncthreads();
    if (wid == 0) {
        int v = (lane < 8) ? sw[lane] : 0;
        #pragma unroll
        for (int o = 4; o > 0; o >>= 1) v += __shfl_down_sync(0xffffffffu, v, o);
        if (lane == 0) g_bsum[blockIdx.x] = v;
    }
}

__global__ void bscan_k(int B) {
    if (threadIdx.x >= 32) return;
    int lane = threadIdx.x;
    int carry = 0;
    for (int base = 0; base < B; base += 32) {
        int v = (base + lane < B) ? g_bsum[base + lane] : 0;
        int incl = v;
        #pragma unroll
        for (int o = 1; o < 32; o <<= 1) {
            int t = __shfl_up_sync(0xffffffffu, incl, o);
            if (lane >= o) incl += t;
        }
        if (base + lane < B) g_bbase[base + lane] = carry + incl - v;
        carry += __shfl_sync(0xffffffffu, incl, 31);
    }
    if (lane == 0) g_bbase[B] = carry;
}

__global__ void offs_k(int n, int B) {
    __shared__ int sw[8];
    int tid = threadIdx.x, lane = tid & 31, wid = tid >> 5;
    int idx = blockIdx.x * SCAN_CHUNK + tid * 4;
    int d0 = 0, d1 = 0, d2 = 0, d3 = 0;
    if (idx + 3 < n) {
        int4 d = *(const int4*)&g_degi[idx];
        d0 = d.x; d1 = d.y; d2 = d.z; d3 = d.w;
    } else {
        if (idx + 0 < n) d0 = g_degi[idx + 0];
        if (idx + 1 < n) d1 = g_degi[idx + 1];
        if (idx + 2 < n) d2 = g_degi[idx + 2];
        if (idx + 3 < n) d3 = g_degi[idx + 3];
    }
    int ls = d0 + d1 + d2 + d3;
    int incl = ls;
    #pragma unroll
    for (int o = 1; o < 32; o <<= 1) {
        int t = __shfl_up_sync(0xffffffffu, incl, o);
        if (lane >= o) incl += t;
    }
    if (lane == 31) sw[wid] = incl;
    __syncthreads();
    if (wid == 0) {
        int v = (lane < 8) ? sw[lane] : 0;
        int vi = v;
        #pragma unroll
        for (int o = 1; o < 8; o <<= 1) {
            int t = __shfl_up_sync(0xffffffffu, vi, o);
            if (lane >= o) vi += t;
        }
        if (lane < 8) sw[lane] = vi - v;
    }
    __syncthreads();
    int excl = g_bbase[blockIdx.x] + sw[wid] + incl - ls;
    if (idx + 0 < n) { g_off[idx + 0] = excl;                g_dinv[idx + 0] = rsqrtf((float)(d0 + 1)); }
    if (idx + 1 < n) { g_off[idx + 1] = excl + d0;           g_dinv[idx + 1] = rsqrtf((float)(d1 + 1)); }
    if (idx + 2 < n) { g_off[idx + 2] = excl + d0 + d1;      g_dinv[idx + 2] = rsqrtf((float)(d2 + 1)); }
    if (idx + 3 < n) { g_off[idx + 3] = excl + d0 + d1 + d2; g_dinv[idx + 3] = rsqrtf((float)(d3 + 1)); }
    if (blockIdx.x == 0 && tid == 0) g_off[n] = g_bbase[B];
}

__global__ void bucket_k(const void* ei, int E) {
    int e = blockIdx.x * blockDim.x + threadIdx.x;
    if (e >= E) return;
    int s = edge_src(ei, E, e);
    int d = edge_dst(ei, E, e);
    int pos = g_off[d] + atomicAdd(&g_cursor[d], 1);
    float w = g_dinv[s] * g_dinv[d];
    g_edge[pos] = make_int2(s, __float_as_int(w));
}

// ---------------- bf16-split tensor-core GEMM: g_H[n,128] = src @ W ----------------
// block 128x128, 8 warps (2M x 4N), warp tile 64x32. K in two 64-halves staged in smem.
__global__ __launch_bounds__(256, 2)
void gemm_bf16_k(const float* __restrict__ Xin, int layer, int src_sel, int n) {
    const float* __restrict__ A = (src_sel == 0) ? Xin : (src_sel == 1 ? g_X1 : g_X2);
    float* __restrict__ C = g_H;

    __shared__ __align__(16) unsigned short Ah[128 * ASTRIDE];
    __shared__ __align__(16) unsigned short Al[128 * ASTRIDE];

    const int tid  = threadIdx.x;
    const int lane = tid & 31, wid = tid >> 5;
    const int gid  = lane >> 2, tig = lane & 3;
    const int warpM  = (wid >> 2) * 64;     // 0 or 64
    const int warpNg = (wid & 3) * 4;       // n8-group base: 0,4,8,12
    const int row0 = blockIdx.x * 128;

    // ldmatrix per-lane tile mapping: t = lane>>3, rows (t&1)*8, kcols (t&2)*4
    const int t8 = lane >> 3, rr = lane & 7;
    const int lrow = ((t8 & 1) << 3) + rr;
    const int lkc  = (t8 & 2) ? 8 : 0;

    uint32_t ah_base = (uint32_t)__cvta_generic_to_shared(Ah);
    uint32_t al_base = (uint32_t)__cvta_generic_to_shared(Al);

    float acc[4][4][4] = {};

    for (int half = 0; half < 2; half++) {
        // fill A half-tile 128 x 64 -> bf16 hi/lo planes
        #pragma unroll
        for (int j = 0; j < 8; j++) {
            int idx = tid + j * 256;
            int r = idx >> 4, q = idx & 15;   // row, float4-index within 64 cols
            float4 v = make_float4(0.f, 0.f, 0.f, 0.f);
            int grow = row0 + r;
            if (grow < n) v = *(const float4*)(A + (size_t)grow * HH + half * 64 + q * 4);
            float h0, l0, h1, l1, h2, l2, h3, l3;
            bsplit(v.x, h0, l0); bsplit(v.y, h1, l1);
            bsplit(v.z, h2, l2); bsplit(v.w, h3, l3);
            uint2 hh = make_uint2(pack_bf(h0, h1), pack_bf(h2, h3));
            uint2 ll = make_uint2(pack_bf(l0, l1), pack_bf(l2, l3));
            *(uint2*)&Ah[r * ASTRIDE + q * 4] = hh;
            *(uint2*)&Al[r * ASTRIDE + q * 4] = ll;
        }
        __syncthreads();

        #pragma unroll
        for (int c = 0; c < 4; c++) {
            int kcol = c * 16;
            // B fragments from precomputed Wfrag (L2-hot)
            uint4 bfz[4];
            #pragma unroll
            for (int nt = 0; nt < 4; nt++)
                bfz[nt] = g_wfrag[(((layer * 8 + half * 4 + c) * 16) + warpNg + nt) * 32 + lane];
            #pragma unroll
            for (int mt = 0; mt < 4; mt++) {
                uint32_t off = (uint32_t)(((warpM + mt * 16 + lrow) * ASTRIDE + kcol + lkc) * 2);
                uint32_t ah[4], al[4];
                LDSM4(ah, ah_base + off);
                LDSM4(al, al_base + off);
                #pragma unroll
                for (int nt = 0; nt < 4; nt++) {
                    MMA_BF16(acc[mt][nt], ah, bfz[nt].x, bfz[nt].y);  // Ah*Bh
                    MMA_BF16(acc[mt][nt], ah, bfz[nt].z, bfz[nt].w);  // Ah*Bl
                    MMA_BF16(acc[mt][nt], al, bfz[nt].x, bfz[nt].y);  // Al*Bh
                }
            }
        }
        __syncthreads();
    }

    #pragma unroll
    for (int mt = 0; mt < 4; mt++) {
        #pragma unroll
        for (int nt = 0; nt < 4; nt++) {
            int r  = row0 + warpM + mt * 16 + gid;
            int cc = (warpNg + nt) * 8 + tig * 2;
            if (r < n)
                *(float2*)(C + (size_t)r * HH + cc) =
                    make_float2(acc[mt][nt][0], acc[mt][nt][1]);
            if (r + 8 < n)
                *(float2*)(C + (size_t)(r + 8) * HH + cc) =
                    make_float2(acc[mt][nt][2], acc[mt][nt][3]);
        }
    }
}

// ---------------- fused aggregate + self-loop + bias + act + residual ----------------
template<int RELU, int RES>
__global__ __launch_bounds__(256)
void agg_k(const float* __restrict__ b, const float* __restrict__ rw,
           int out_sel, int n) {
    float* __restrict__ Xout = out_sel ? g_X2 : g_X1;
    const float* __restrict__ Xres = out_sel ? g_X1 : g_X2;
    const float* __restrict__ H = g_H;

    int node = blockIdx.x * (blockDim.x >> 5) + (threadIdx.x >> 5);
    if (node >= n) return;
    int lane = threadIdx.x & 31;
    int beg = __ldg(&g_off[node]);
    int end = __ldg(&g_off[node + 1]);

    float ax = 0.f, ay = 0.f, az = 0.f, aw = 0.f;
    int e = beg;
    for (; e + 1 < end; e += 2) {
        int2 e0 = __ldg(&g_edge[e]);
        int2 e1 = __ldg(&g_edge[e + 1]);
        float w0 = __int_as_float(e0.y);
        float w1 = __int_as_float(e1.y);
        float4 v0 = *(const float4*)(H + (size_t)e0.x * HH + lane * 4);
        float4 v1 = *(const float4*)(H + (size_t)e1.x * HH + lane * 4);
        ax += w0 * v0.x + w1 * v1.x;
        ay += w0 * v0.y + w1 * v1.y;
        az += w0 * v0.z + w1 * v1.z;
        aw += w0 * v0.w + w1 * v1.w;
    }
    if (e < end) {
        int2 e0 = __ldg(&g_edge[e]);
        float w0 = __int_as_float(e0.y);
        float4 v0 = *(const float4*)(H + (size_t)e0.x * HH + lane * 4);
        ax += w0 * v0.x; ay += w0 * v0.y; az += w0 * v0.z; aw += w0 * v0.w;
    }

    float dv = __ldg(&g_dinv[node]);
    float sn = dv * dv;
    float4 h  = *(const float4*)(H + (size_t)node * HH + lane * 4);
    float4 bb = *(const float4*)(b + lane * 4);
    float vx = ax + sn * h.x + bb.x;
    float vy = ay + sn * h.y + bb.y;
    float vz = az + sn * h.z + bb.z;
    float vw = aw + sn * h.w + bb.w;
    if (RELU) {
        vx = fmaxf(vx, 0.f); vy = fmaxf(vy, 0.f);
        vz = fmaxf(vz, 0.f); vw = fmaxf(vw, 0.f);
    }
    if (RES) {
        float w = *rw;
        float4 r = *(const float4*)(Xres + (size_t)node * HH + lane * 4);
        vx += w * r.x; vy += w * r.y; vz += w * r.z; vw += w * r.w;
    }
    *(float4*)(Xout + (size_t)node * HH + lane * 4) = make_float4(vx, vy, vz, vw);
}

// ---------------- head ----------------
__global__ void head_k(const float* __restrict__ W, const float* __restrict__ b,
                       float* __restrict__ out, int n) {
    int idx = blockIdx.x * blockDim.x + threadIdx.x;
    if (idx >= n * CC) return;
    int node = idx / CC;
    int c    = idx % CC;
    const float* xr = g_X2 + (size_t)node * HH;
    float a0 = 0.f, a1 = 0.f, a2 = 0.f, a3 = 0.f;
    #pragma unroll
    for (int k = 0; k < HH; k += 4) {
        a0 += xr[k + 0] * __ldg(W + (k + 0) * CC + c);
        a1 += xr[k + 1] * __ldg(W + (k + 1) * CC + c);
        a2 += xr[k + 2] * __ldg(W + (k + 2) * CC + c);
        a3 += xr[k + 3] * __ldg(W + (k + 3) * CC + c);
    }
    out[idx] = (a0 + a1) + (a2 + a3) + b[c];
}

// ---------------- launch ----------------
extern "C" void kernel_launch(void* const* d_in, const int* in_sizes, int n_in,
                              void* d_out, int out_size) {
    const float* X    = (const float*)d_in[0];
    const void*  ei   = d_in[1];
    const float* Ws   = (const float*)d_in[2];
    const float* bs   = (const float*)d_in[3];
    const float* mlpW = (const float*)d_in[4];
    const float* mlpb = (const float*)d_in[5];
    const float* rw   = (const float*)d_in[6];
    float* out = (float*)d_out;

    int n = in_sizes[0] / HH;
    int E = in_sizes[1] / 2;

    const int T = 256;
    int B = (n + SCAN_CHUNK - 1) / SCAN_CHUNK;

    init_k <<<(n + T - 1) / T, T>>>(ei, E, n);
    wfrag_k<<<(4 * 8 * 16 * 32 + T - 1) / T, T>>>(Ws);
    hist_k <<<(E + T - 1) / T, T>>>(ei, E);
    bsum_k <<<B, 256>>>(n);
    bscan_k<<<1, 32>>>(B);
    offs_k <<<B, 256>>>(n, B);
    bucket_k<<<(E + T - 1) / T, T>>>(ei, E);

    int gblocks = (n + 127) / 128;
    int ablocks = (n + 7) / 8;

    gemm_bf16_k<<<gblocks, T>>>(X, 0, 0, n);
    agg_k<1, 0><<<ablocks, T>>>(bs + 0 * HH, rw, 0, n);
    gemm_bf16_k<<<gblocks, T>>>(X, 1, 1, n);
    agg_k<1, 1><<<ablocks, T>>>(bs + 1 * HH, rw, 1, n);
    gemm_bf16_k<<<gblocks, T>>>(X, 2, 2, n);
    agg_k<1, 1><<<ablocks, T>>>(bs + 2 * HH, rw, 0, n);
    gemm_bf16_k<<<gblocks, T>>>(X, 3, 1, n);
    agg_k<0, 0><<<ablocks, T>>>(bs + 3 * HH, rw, 1, n);

    head_k<<<(n * CC + T - 1) / T, T>>>(mlpW, mlpb, out, n);
}

// round 16
// speedup vs baseline: 2.1319x; 1.0626x over previous
#include <cuda_runtime.h>
#include <cuda_bf16.h>
#include <cuda_fp16.h>
#include <stdint.h>

#define NMAX 50000
#define HH   128
#define EMAX 800000
#define CC   40
#define SCAN_CHUNK 1024
#define ASTRIDE 72

// ---------------- scratch ----------------
__device__ int   g_is32;
__device__ int   g_degi  [NMAX];
__device__ int   g_off   [NMAX + 1];
__device__ int   g_cursor[NMAX];
__device__ float g_dinv  [NMAX];
__device__ int   g_bsum  [(NMAX + SCAN_CHUNK - 1) / SCAN_CHUNK];
__device__ int   g_bbase [(NMAX + SCAN_CHUNK - 1) / SCAN_CHUNK + 1];
__device__ __align__(8) int2 g_edge[EMAX];
__device__ __align__(16) uint4 g_wfrag[4 * 8 * 16 * 32];
__device__ __align__(16) __half g_Hh[NMAX * HH];          // fp16 hidden activations
__device__ __align__(16) float g_X1[NMAX * HH];
__device__ __align__(16) float g_X2[NMAX * HH];

// ---------------- helpers ----------------
__device__ __forceinline__ int edge_src(const void* ei, int E, int e) {
    return g_is32 ? ((const int*)ei)[e] : (int)((const long long*)ei)[e];
}
__device__ __forceinline__ int edge_dst(const void* ei, int E, int e) {
    return g_is32 ? ((const int*)ei)[E + e] : (int)((const long long*)ei)[E + e];
}

__device__ __forceinline__ uint32_t pack_bf(float a, float b) {
    __nv_bfloat162 t = __floats2bfloat162_rn(a, b);
    return *(uint32_t*)&t;
}
__device__ __forceinline__ void bsplit(float x, float& hi, float& lo) {
    __nv_bfloat16 h = __float2bfloat16_rn(x);
    hi = __bfloat162float(h);
    lo = x - hi;
}

#define MMA_BF16(c, a, b0, b1) \
    asm volatile("mma.sync.aligned.m16n8k16.row.col.f32.bf16.bf16.f32 " \
        "{%0,%1,%2,%3},{%4,%5,%6,%7},{%8,%9},{%0,%1,%2,%3};" \
        : "+f"((c)[0]), "+f"((c)[1]), "+f"((c)[2]), "+f"((c)[3]) \
        : "r"((a)[0]), "r"((a)[1]), "r"((a)[2]), "r"((a)[3]), "r"(b0), "r"(b1))

#define LDSM4(r, addr) \
    asm volatile("ldmatrix.sync.aligned.m8n8.x4.shared.b16 {%0,%1,%2,%3}, [%4];" \
        : "=r"((r)[0]), "=r"((r)[1]), "=r"((r)[2]), "=r"((r)[3]) : "r"(addr))

// ---------------- CSR build ----------------
__global__ void init_k(const void* ei, int E, int n) {
    int i = blockIdx.x * blockDim.x + threadIdx.x;
    if (i < n) { g_degi[i] = 0; g_cursor[i] = 0; }
    if (blockIdx.x == 0 && threadIdx.x < 32) {
        const long long* p = (const long long*)ei;
        int lim = (E < 32) ? E : 32;
        long long v = (threadIdx.x < lim) ? p[threadIdx.x] : 0;
        unsigned bad = __ballot_sync(0xffffffffu, v < 0 || v >= (long long)n);
        if (threadIdx.x == 0) g_is32 = bad ? 1 : 0;
    }
}

__global__ void wfrag_k(const float* __restrict__ Ws) {
    int i = blockIdx.x * blockDim.x + threadIdx.x;
    if (i >= 4 * 8 * 16 * 32) return;
    int l = i & 31, g = (i >> 5) & 15, c = (i >> 9) & 7, layer = i >> 12;
    int nn = g * 8 + (l >> 2);
    int kb = c * 16 + (l & 3) * 2;
    const float* W = Ws + (size_t)layer * HH * HH;
    float w0 = W[(kb + 0) * HH + nn], w1 = W[(kb + 1) * HH + nn];
    float w2 = W[(kb + 8) * HH + nn], w3 = W[(kb + 9) * HH + nn];
    float h0, l0, h1, l1, h2, l2, h3, l3;
    bsplit(w0, h0, l0); bsplit(w1, h1, l1); bsplit(w2, h2, l2); bsplit(w3, h3, l3);
    uint4 o;
    o.x = pack_bf(h0, h1); o.y = pack_bf(h2, h3);
    o.z = pack_bf(l0, l1); o.w = pack_bf(l2, l3);
    g_wfrag[i] = o;
}

__global__ void hist_k(const void* ei, int E) {
    int e = blockIdx.x * blockDim.x + threadIdx.x;
    if (e < E) atomicAdd(&g_degi[edge_dst(ei, E, e)], 1);
}

__global__ void bsum_k(int n) {
    __shared__ int sw[8];
    int tid = threadIdx.x, lane = tid & 31, wid = tid >> 5;
    int idx = blockIdx.x * SCAN_CHUNK + tid * 4;
    int s = 0;
    if (idx + 3 < n) {
        int4 d = *(const int4*)&g_degi[idx];
        s = d.x + d.y + d.z + d.w;
    } else {
        for (int j = 0; j < 4; j++) if (idx + j < n) s += g_degi[idx + j];
    }
    #pragma unroll
    for (int o = 16; o > 0; o >>= 1) s += __shfl_down_sync(0xffffffffu, s, o);
    if (lane == 0) sw[wid] = s;
    __syncthreads();
    if (wid == 0) {
        int v = (lane < 8) ? sw[lane] : 0;
        #pragma unroll
        for (int o = 4; o > 0; o >>= 1) v += __shfl_down_sync(0xffffffffu, v, o);
        if (lane == 0) g_bsum[blockIdx.x] = v;
    }
}

__global__ void bscan_k(int B) {
    if (threadIdx.x >= 32) return;
    int lane = threadIdx.x;
    int carry = 0;
    for (int base = 0; base < B; base += 32) {
        int v = (base + lane < B) ? g_bsum[base + lane] : 0;
        int incl = v;
        #pragma unroll
        for (int o = 1; o < 32; o <<= 1) {
            int t = __shfl_up_sync(0xffffffffu, incl, o);
            if (lane >= o) incl += t;
        }
        if (base + lane < B) g_bbase[base + lane] = carry + incl - v;
        carry += __shfl_sync(0xffffffffu, incl, 31);
    }
    if (lane == 0) g_bbase[B] = carry;
}

__global__ void offs_k(int n, int B) {
    __shared__ int sw[8];
    int tid = threadIdx.x, lane = tid & 31, wid = tid >> 5;
    int idx = blockIdx.x * SCAN_CHUNK + tid * 4;
    int d0 = 0, d1 = 0, d2 = 0, d3 = 0;
    if (idx + 3 < n) {
        int4 d = *(const int4*)&g_degi[idx];
        d0 = d.x; d1 = d.y; d2 = d.z; d3 = d.w;
    } else {
        if (idx + 0 < n) d0 = g_degi[idx + 0];
        if (idx + 1 < n) d1 = g_degi[idx + 1];
        if (idx + 2 < n) d2 = g_degi[idx + 2];
        if (idx + 3 < n) d3 = g_degi[idx + 3];
    }
    int ls = d0 + d1 + d2 + d3;
    int incl = ls;
    #pragma unroll
    for (int o = 1; o < 32; o <<= 1) {
        int t = __shfl_up_sync(0xffffffffu, incl, o);
        if (lane >= o) incl += t;
    }
    if (lane == 31) sw[wid] = incl;
    __syncthreads();
    if (wid == 0) {
        int v = (lane < 8) ? sw[lane] : 0;
        int vi = v;
        #pragma unroll
        for (int o = 1; o < 8; o <<= 1) {
            int t = __shfl_up_sync(0xffffffffu, vi, o);
            if (lane >= o) vi += t;
        }
        if (lane < 8) sw[lane] = vi - v;
    }
    __syncthreads();
    int excl = g_bbase[blockIdx.x] + sw[wid] + incl - ls;
    if (idx + 0 < n) { g_off[idx + 0] = excl;                g_dinv[idx + 0] = rsqrtf((float)(d0 + 1)); }
    if (idx + 1 < n) { g_off[idx + 1] = excl + d0;           g_dinv[idx + 1] = rsqrtf((float)(d1 + 1)); }
    if (idx + 2 < n) { g_off[idx + 2] = excl + d0 + d1;      g_dinv[idx + 2] = rsqrtf((float)(d2 + 1)); }
    if (idx + 3 < n) { g_off[idx + 3] = excl + d0 + d1 + d2; g_dinv[idx + 3] = rsqrtf((float)(d3 + 1)); }
    if (blockIdx.x == 0 && tid == 0) g_off[n] = g_bbase[B];
}

__global__ void bucket_k(const void* ei, int E) {
    int e = blockIdx.x * blockDim.x + threadIdx.x;
    if (e >= E) return;
    int s = edge_src(ei, E, e);
    int d = edge_dst(ei, E, e);
    int pos = g_off[d] + atomicAdd(&g_cursor[d], 1);
    float w = g_dinv[s] * g_dinv[d];
    g_edge[pos] = make_int2(s, __float_as_int(w));
}

// ---------------- bf16-split TC GEMM: g_Hh[n,128] = fp16(src @ W) ----------------
__global__ __launch_bounds__(256, 2)
void gemm_bf16_k(const float* __restrict__ Xin, int layer, int src_sel, int n) {
    const float* __restrict__ A = (src_sel == 0) ? Xin : (src_sel == 1 ? g_X1 : g_X2);

    __shared__ __align__(16) unsigned short Ah[128 * ASTRIDE];
    __shared__ __align__(16) unsigned short Al[128 * ASTRIDE];

    const int tid  = threadIdx.x;
    const int lane = tid & 31, wid = tid >> 5;
    const int gid  = lane >> 2, tig = lane & 3;
    const int warpM  = (wid >> 2) * 64;
    const int warpNg = (wid & 3) * 4;
    const int row0 = blockIdx.x * 128;

    const int t8 = lane >> 3, rr = lane & 7;
    const int lrow = ((t8 & 1) << 3) + rr;
    const int lkc  = (t8 & 2) ? 8 : 0;

    uint32_t ah_base = (uint32_t)__cvta_generic_to_shared(Ah);
    uint32_t al_base = (uint32_t)__cvta_generic_to_shared(Al);

    float acc[4][4][4] = {};

    for (int half = 0; half < 2; half++) {
        #pragma unroll
        for (int j = 0; j < 8; j++) {
            int idx = tid + j * 256;
            int r = idx >> 4, q = idx & 15;
            float4 v = make_float4(0.f, 0.f, 0.f, 0.f);
            int grow = row0 + r;
            if (grow < n) v = *(const float4*)(A + (size_t)grow * HH + half * 64 + q * 4);
            float h0, l0, h1, l1, h2, l2, h3, l3;
            bsplit(v.x, h0, l0); bsplit(v.y, h1, l1);
            bsplit(v.z, h2, l2); bsplit(v.w, h3, l3);
            uint2 hh = make_uint2(pack_bf(h0, h1), pack_bf(h2, h3));
            uint2 ll = make_uint2(pack_bf(l0, l1), pack_bf(l2, l3));
            *(uint2*)&Ah[r * ASTRIDE + q * 4] = hh;
            *(uint2*)&Al[r * ASTRIDE + q * 4] = ll;
        }
        __syncthreads();

        #pragma unroll
        for (int c = 0; c < 4; c++) {
            int kcol = c * 16;
            uint4 bfz[4];
            #pragma unroll
            for (int nt = 0; nt < 4; nt++)
                bfz[nt] = g_wfrag[(((layer * 8 + half * 4 + c) * 16) + warpNg + nt) * 32 + lane];
            #pragma unroll
            for (int mt = 0; mt < 4; mt++) {
                uint32_t off = (uint32_t)(((warpM + mt * 16 + lrow) * ASTRIDE + kcol + lkc) * 2);
                uint32_t ah[4], al[4];
                LDSM4(ah, ah_base + off);
                LDSM4(al, al_base + off);
                #pragma unroll
                for (int nt = 0; nt < 4; nt++) {
                    MMA_BF16(acc[mt][nt], ah, bfz[nt].x, bfz[nt].y);
                    MMA_BF16(acc[mt][nt], ah, bfz[nt].z, bfz[nt].w);
                    MMA_BF16(acc[mt][nt], al, bfz[nt].x, bfz[nt].y);
                }
            }
        }
        __syncthreads();
    }

    // fp16 epilogue store
    #pragma unroll
    for (int mt = 0; mt < 4; mt++) {
        #pragma unroll
        for (int nt = 0; nt < 4; nt++) {
            int r  = row0 + warpM + mt * 16 + gid;
            int cc = (warpNg + nt) * 8 + tig * 2;
            if (r < n)
                *(__half2*)(g_Hh + (size_t)r * HH + cc) =
                    __floats2half2_rn(acc[mt][nt][0], acc[mt][nt][1]);
            if (r + 8 < n)
                *(__half2*)(g_Hh + (size_t)(r + 8) * HH + cc) =
                    __floats2half2_rn(acc[mt][nt][2], acc[mt][nt][3]);
        }
    }
}

// ---------------- fused aggregate (fp16 gathers) ----------------
template<int RELU, int RES>
__global__ __launch_bounds__(256)
void agg_k(const float* __restrict__ b, const float* __restrict__ rw,
           int out_sel, int n) {
    float* __restrict__ Xout = out_sel ? g_X2 : g_X1;
    const float* __restrict__ Xres = out_sel ? g_X1 : g_X2;
    const __half* __restrict__ H = g_Hh;

    int node = blockIdx.x * (blockDim.x >> 5) + (threadIdx.x >> 5);
    if (node >= n) return;
    int lane = threadIdx.x & 31;
    int beg = __ldg(&g_off[node]);
    int end = __ldg(&g_off[node + 1]);

    float ax = 0.f, ay = 0.f, az = 0.f, aw = 0.f;
    int e = beg;
    for (; e + 1 < end; e += 2) {
        int2 e0 = __ldg(&g_edge[e]);
        int2 e1 = __ldg(&g_edge[e + 1]);
        float w0 = __int_as_float(e0.y);
        float w1 = __int_as_float(e1.y);
        uint2 r0 = *(const uint2*)(H + (size_t)e0.x * HH + lane * 4);
        uint2 r1 = *(const uint2*)(H + (size_t)e1.x * HH + lane * 4);
        float2 f00 = __half22float2(*(__half2*)&r0.x);
        float2 f01 = __half22float2(*(__half2*)&r0.y);
        float2 f10 = __half22float2(*(__half2*)&r1.x);
        float2 f11 = __half22float2(*(__half2*)&r1.y);
        ax += w0 * f00.x + w1 * f10.x;
        ay += w0 * f00.y + w1 * f10.y;
        az += w0 * f01.x + w1 * f11.x;
        aw += w0 * f01.y + w1 * f11.y;
    }
    if (e < end) {
        int2 e0 = __ldg(&g_edge[e]);
        float w0 = __int_as_float(e0.y);
        uint2 r0 = *(const uint2*)(H + (size_t)e0.x * HH + lane * 4);
        float2 f00 = __half22float2(*(__half2*)&r0.x);
        float2 f01 = __half22float2(*(__half2*)&r0.y);
        ax += w0 * f00.x; ay += w0 * f00.y; az += w0 * f01.x; aw += w0 * f01.y;
    }

    float dv = __ldg(&g_dinv[node]);
    float sn = dv * dv;
    uint2 rs = *(const uint2*)(H + (size_t)node * HH + lane * 4);
    float2 s0 = __half22float2(*(__half2*)&rs.x);
    float2 s1 = __half22float2(*(__half2*)&rs.y);
    float4 bb = *(const float4*)(b + lane * 4);
    float vx = ax + sn * s0.x + bb.x;
    float vy = ay + sn * s0.y + bb.y;
    float vz = az + sn * s1.x + bb.z;
    float vw = aw + sn * s1.y + bb.w;
    if (RELU) {
        vx = fmaxf(vx, 0.f); vy = fmaxf(vy, 0.f);
        vz = fmaxf(vz, 0.f); vw = fmaxf(vw, 0.f);
    }
    if (RES) {
        float w = *rw;
        float4 r = *(const float4*)(Xres + (size_t)node * HH + lane * 4);
        vx += w * r.x; vy += w * r.y; vz += w * r.z; vw += w * r.w;
    }
    *(float4*)(Xout + (size_t)node * HH + lane * 4) = make_float4(vx, vy, vz, vw);
}

// ---------------- head ----------------
__global__ void head_k(const float* __restrict__ W, const float* __restrict__ b,
                       float* __restrict__ out, int n) {
    int idx = blockIdx.x * blockDim.x + threadIdx.x;
    if (idx >= n * CC) return;
    int node = idx / CC;
    int c    = idx % CC;
    const float* xr = g_X2 + (size_t)node * HH;
    float a0 = 0.f, a1 = 0.f, a2 = 0.f, a3 = 0.f;
    #pragma unroll
    for (int k = 0; k < HH; k += 4) {
        a0 += xr[k + 0] * __ldg(W + (k + 0) * CC + c);
        a1 += xr[k + 1] * __ldg(W + (k + 1) * CC + c);
        a2 += xr[k + 2] * __ldg(W + (k + 2) * CC + c);
        a3 += xr[k + 3] * __ldg(W + (k + 3) * CC + c);
    }
    out[idx] = (a0 + a1) + (a2 + a3) + b[c];
}

// ---------------- launch ----------------
extern "C" void kernel_launch(void* const* d_in, const int* in_sizes, int n_in,
                              void* d_out, int out_size) {
    const float* X    = (const float*)d_in[0];
    const void*  ei   = d_in[1];
    const float* Ws   = (const float*)d_in[2];
    const float* bs   = (const float*)d_in[3];
    const float* mlpW = (const float*)d_in[4];
    const float* mlpb = (const float*)d_in[5];
    const float* rw   = (const float*)d_in[6];
    float* out = (float*)d_out;

    int n = in_sizes[0] / HH;
    int E = in_sizes[1] / 2;

    const int T = 256;
    int B = (n + SCAN_CHUNK - 1) / SCAN_CHUNK;

    init_k <<<(n + T - 1) / T, T>>>(ei, E, n);
    wfrag_k<<<(4 * 8 * 16 * 32 + T - 1) / T, T>>>(Ws);
    hist_k <<<(E + T - 1) / T, T>>>(ei, E);
    bsum_k <<<B, 256>>>(n);
    bscan_k<<<1, 32>>>(B);
    offs_k <<<B, 256>>>(n, B);
    bucket_k<<<(E + T - 1) / T, T>>>(ei, E);

    int gblocks = (n + 127) / 128;
    int ablocks = (n + 7) / 8;

    gemm_bf16_k<<<gblocks, T>>>(X, 0, 0, n);
    agg_k<1, 0><<<ablocks, T>>>(bs + 0 * HH, rw, 0, n);
    gemm_bf16_k<<<gblocks, T>>>(X, 1, 1, n);
    agg_k<1, 1><<<ablocks, T>>>(bs + 1 * HH, rw, 1, n);
    gemm_bf16_k<<<gblocks, T>>>(X, 2, 2, n);
    agg_k<1, 1><<<ablocks, T>>>(bs + 2 * HH, rw, 0, n);
    gemm_bf16_k<<<gblocks, T>>>(X, 3, 1, n);
    agg_k<0, 0><<<ablocks, T>>>(bs + 3 * HH, rw, 1, n);

    head_k<<<(n * CC + T - 1) / T, T>>>(mlpW, mlpb, out, n);
}

// round 17
// speedup vs baseline: 2.1611x; 1.0137x over previous
#include <cuda_runtime.h>
#include <cuda_bf16.h>
#include <cuda_fp16.h>
#include <stdint.h>

#define NMAX 50000
#define HH   128
#define EMAX 800000
#define CC   40
#define SCAN_CHUNK 1024
#define ASTRIDE 72

// ---------------- scratch ----------------
__device__ int   g_is32;
__device__ int   g_degi  [NMAX];
__device__ int   g_off   [NMAX + 1];
__device__ int   g_cursor[NMAX];
__device__ float g_dinv  [NMAX];
__device__ int   g_bsum  [(NMAX + SCAN_CHUNK - 1) / SCAN_CHUNK];
__device__ int   g_bbase [(NMAX + SCAN_CHUNK - 1) / SCAN_CHUNK + 1];
__device__ __align__(8) int2 g_edge[EMAX];
__device__ __align__(16) uint4 g_wfrag[4 * 8 * 16 * 32];
__device__ __align__(16) __half g_Hh[NMAX * HH];   // fp16 post-GEMM activations
__device__ __align__(16) __half g_X1[NMAX * HH];   // fp16 layer outputs (ping)
__device__ __align__(16) __half g_X2[NMAX * HH];   // fp16 layer outputs (pong)

// ---------------- helpers ----------------
__device__ __forceinline__ int edge_src(const void* ei, int E, int e) {
    return g_is32 ? ((const int*)ei)[e] : (int)((const long long*)ei)[e];
}
__device__ __forceinline__ int edge_dst(const void* ei, int E, int e) {
    return g_is32 ? ((const int*)ei)[E + e] : (int)((const long long*)ei)[E + e];
}

__device__ __forceinline__ uint32_t pack_bf(float a, float b) {
    __nv_bfloat162 t = __floats2bfloat162_rn(a, b);
    return *(uint32_t*)&t;
}
__device__ __forceinline__ void bsplit(float x, float& hi, float& lo) {
    __nv_bfloat16 h = __float2bfloat16_rn(x);
    hi = __bfloat162float(h);
    lo = x - hi;
}

#define MMA_BF16(c, a, b0, b1) \
    asm volatile("mma.sync.aligned.m16n8k16.row.col.f32.bf16.bf16.f32 " \
        "{%0,%1,%2,%3},{%4,%5,%6,%7},{%8,%9},{%0,%1,%2,%3};" \
        : "+f"((c)[0]), "+f"((c)[1]), "+f"((c)[2]), "+f"((c)[3]) \
        : "r"((a)[0]), "r"((a)[1]), "r"((a)[2]), "r"((a)[3]), "r"(b0), "r"(b1))

#define LDSM4(r, addr) \
    asm volatile("ldmatrix.sync.aligned.m8n8.x4.shared.b16 {%0,%1,%2,%3}, [%4];" \
        : "=r"((r)[0]), "=r"((r)[1]), "=r"((r)[2]), "=r"((r)[3]) : "r"(addr))

// ---------------- CSR build ----------------
__global__ void init_k(const void* ei, int E, int n) {
    int i = blockIdx.x * blockDim.x + threadIdx.x;
    if (i < n) { g_degi[i] = 0; g_cursor[i] = 0; }
    if (blockIdx.x == 0 && threadIdx.x < 32) {
        const long long* p = (const long long*)ei;
        int lim = (E < 32) ? E : 32;
        long long v = (threadIdx.x < lim) ? p[threadIdx.x] : 0;
        unsigned bad = __ballot_sync(0xffffffffu, v < 0 || v >= (long long)n);
        if (threadIdx.x == 0) g_is32 = bad ? 1 : 0;
    }
}

__global__ void wfrag_k(const float* __restrict__ Ws) {
    int i = blockIdx.x * blockDim.x + threadIdx.x;
    if (i >= 4 * 8 * 16 * 32) return;
    int l = i & 31, g = (i >> 5) & 15, c = (i >> 9) & 7, layer = i >> 12;
    int nn = g * 8 + (l >> 2);
    int kb = c * 16 + (l & 3) * 2;
    const float* W = Ws + (size_t)layer * HH * HH;
    float w0 = W[(kb + 0) * HH + nn], w1 = W[(kb + 1) * HH + nn];
    float w2 = W[(kb + 8) * HH + nn], w3 = W[(kb + 9) * HH + nn];
    float h0, l0, h1, l1, h2, l2, h3, l3;
    bsplit(w0, h0, l0); bsplit(w1, h1, l1); bsplit(w2, h2, l2); bsplit(w3, h3, l3);
    uint4 o;
    o.x = pack_bf(h0, h1); o.y = pack_bf(h2, h3);
    o.z = pack_bf(l0, l1); o.w = pack_bf(l2, l3);
    g_wfrag[i] = o;
}

__global__ void hist_k(const void* ei, int E) {
    int e = blockIdx.x * blockDim.x + threadIdx.x;
    if (e < E) atomicAdd(&g_degi[edge_dst(ei, E, e)], 1);
}

__global__ void bsum_k(int n) {
    __shared__ int sw[8];
    int tid = threadIdx.x, lane = tid & 31, wid = tid >> 5;
    int idx = blockIdx.x * SCAN_CHUNK + tid * 4;
    int s = 0;
    if (idx + 3 < n) {
        int4 d = *(const int4*)&g_degi[idx];
        s = d.x + d.y + d.z + d.w;
    } else {
        for (int j = 0; j < 4; j++) if (idx + j < n) s += g_degi[idx + j];
    }
    #pragma unroll
    for (int o = 16; o > 0; o >>= 1) s += __shfl_down_sync(0xffffffffu, s, o);
    if (lane == 0) sw[wid] = s;
    __syncthreads();
    if (wid == 0) {
        int v = (lane < 8) ? sw[lane] : 0;
        #pragma unroll
        for (int o = 4; o > 0; o >>= 1) v += __shfl_down_sync(0xffffffffu, v, o);
        if (lane == 0) g_bsum[blockIdx.x] = v;
    }
}

__global__ void bscan_k(int B) {
    if (threadIdx.x >= 32) return;
    int lane = threadIdx.x;
    int carry = 0;
    for (int base = 0; base < B; base += 32) {
        int v = (base + lane < B) ? g_bsum[base + lane] : 0;
        int incl = v;
        #pragma unroll
        for (int o = 1; o < 32; o <<= 1) {
            int t = __shfl_up_sync(0xffffffffu, incl, o);
            if (lane >= o) incl += t;
        }
        if (base + lane < B) g_bbase[base + lane] = carry + incl - v;
        carry += __shfl_sync(0xffffffffu, incl, 31);
    }
    if (lane == 0) g_bbase[B] = carry;
}

__global__ void offs_k(int n, int B) {
    __shared__ int sw[8];
    int tid = threadIdx.x, lane = tid & 31, wid = tid >> 5;
    int idx = blockIdx.x * SCAN_CHUNK + tid * 4;
    int d0 = 0, d1 = 0, d2 = 0, d3 = 0;
    if (idx + 3 < n) {
        int4 d = *(const int4*)&g_degi[idx];
        d0 = d.x; d1 = d.y; d2 = d.z; d3 = d.w;
    } else {
        if (idx + 0 < n) d0 = g_degi[idx + 0];
        if (idx + 1 < n) d1 = g_degi[idx + 1];
        if (idx + 2 < n) d2 = g_degi[idx + 2];
        if (idx + 3 < n) d3 = g_degi[idx + 3];
    }
    int ls = d0 + d1 + d2 + d3;
    int incl = ls;
    #pragma unroll
    for (int o = 1; o < 32; o <<= 1) {
        int t = __shfl_up_sync(0xffffffffu, incl, o);
        if (lane >= o) incl += t;
    }
    if (lane == 31) sw[wid] = incl;
    __syncthreads();
    if (wid == 0) {
        int v = (lane < 8) ? sw[lane] : 0;
        int vi = v;
        #pragma unroll
        for (int o = 1; o < 8; o <<= 1) {
            int t = __shfl_up_sync(0xffffffffu, vi, o);
            if (lane >= o) vi += t;
        }
        if (lane < 8) sw[lane] = vi - v;
    }
    __syncthreads();
    int excl = g_bbase[blockIdx.x] + sw[wid] + incl - ls;
    if (idx + 0 < n) { g_off[idx + 0] = excl;                g_dinv[idx + 0] = rsqrtf((float)(d0 + 1)); }
    if (idx + 1 < n) { g_off[idx + 1] = excl + d0;           g_dinv[idx + 1] = rsqrtf((float)(d1 + 1)); }
    if (idx + 2 < n) { g_off[idx + 2] = excl + d0 + d1;      g_dinv[idx + 2] = rsqrtf((float)(d2 + 1)); }
    if (idx + 3 < n) { g_off[idx + 3] = excl + d0 + d1 + d2; g_dinv[idx + 3] = rsqrtf((float)(d3 + 1)); }
    if (blockIdx.x == 0 && tid == 0) g_off[n] = g_bbase[B];
}

__global__ void bucket_k(const void* ei, int E) {
    int e = blockIdx.x * blockDim.x + threadIdx.x;
    if (e >= E) return;
    int s = edge_src(ei, E, e);
    int d = edge_dst(ei, E, e);
    int pos = g_off[d] + atomicAdd(&g_cursor[d], 1);
    float w = g_dinv[s] * g_dinv[d];
    g_edge[pos] = make_int2(s, __float_as_int(w));
}

// ---------------- bf16-split TC GEMM: g_Hh[n,128] = fp16(src @ W) ----------------
// src_sel: 0 = fp32 X input, 1 = g_X1 (fp16), 2 = g_X2 (fp16)
__global__ __launch_bounds__(256, 2)
void gemm_bf16_k(const float* __restrict__ Xin, int layer, int src_sel, int n) {
    const __half* __restrict__ Ah16 = (src_sel == 1) ? g_X1 : g_X2;

    __shared__ __align__(16) unsigned short Ah[128 * ASTRIDE];
    __shared__ __align__(16) unsigned short Al[128 * ASTRIDE];

    const int tid  = threadIdx.x;
    const int lane = tid & 31, wid = tid >> 5;
    const int gid  = lane >> 2, tig = lane & 3;
    const int warpM  = (wid >> 2) * 64;
    const int warpNg = (wid & 3) * 4;
    const int row0 = blockIdx.x * 128;

    const int t8 = lane >> 3, rr = lane & 7;
    const int lrow = ((t8 & 1) << 3) + rr;
    const int lkc  = (t8 & 2) ? 8 : 0;

    uint32_t ah_base = (uint32_t)__cvta_generic_to_shared(Ah);
    uint32_t al_base = (uint32_t)__cvta_generic_to_shared(Al);

    float acc[4][4][4] = {};

    for (int half = 0; half < 2; half++) {
        #pragma unroll
        for (int j = 0; j < 8; j++) {
            int idx = tid + j * 256;
            int r = idx >> 4, q = idx & 15;
            float4 v = make_float4(0.f, 0.f, 0.f, 0.f);
            int grow = row0 + r;
            if (grow < n) {
                if (src_sel == 0) {
                    v = *(const float4*)(Xin + (size_t)grow * HH + half * 64 + q * 4);
                } else {
                    uint2 p = *(const uint2*)(Ah16 + (size_t)grow * HH + half * 64 + q * 4);
                    float2 f0 = __half22float2(*(__half2*)&p.x);
                    float2 f1 = __half22float2(*(__half2*)&p.y);
                    v = make_float4(f0.x, f0.y, f1.x, f1.y);
                }
            }
            float h0, l0, h1, l1, h2, l2, h3, l3;
            bsplit(v.x, h0, l0); bsplit(v.y, h1, l1);
            bsplit(v.z, h2, l2); bsplit(v.w, h3, l3);
            uint2 hh = make_uint2(pack_bf(h0, h1), pack_bf(h2, h3));
            uint2 ll = make_uint2(pack_bf(l0, l1), pack_bf(l2, l3));
            *(uint2*)&Ah[r * ASTRIDE + q * 4] = hh;
            *(uint2*)&Al[r * ASTRIDE + q * 4] = ll;
        }
        __syncthreads();

        #pragma unroll
        for (int c = 0; c < 4; c++) {
            int kcol = c * 16;
            uint4 bfz[4];
            #pragma unroll
            for (int nt = 0; nt < 4; nt++)
                bfz[nt] = g_wfrag[(((layer * 8 + half * 4 + c) * 16) + warpNg + nt) * 32 + lane];
            #pragma unroll
            for (int mt = 0; mt < 4; mt++) {
                uint32_t off = (uint32_t)(((warpM + mt * 16 + lrow) * ASTRIDE + kcol + lkc) * 2);
                uint32_t ah[4], al[4];
                LDSM4(ah, ah_base + off);
                LDSM4(al, al_base + off);
                #pragma unroll
                for (int nt = 0; nt < 4; nt++) {
                    MMA_BF16(acc[mt][nt], ah, bfz[nt].x, bfz[nt].y);
                    MMA_BF16(acc[mt][nt], ah, bfz[nt].z, bfz[nt].w);
                    MMA_BF16(acc[mt][nt], al, bfz[nt].x, bfz[nt].y);
                }
            }
        }
        __syncthreads();
    }

    #pragma unroll
    for (int mt = 0; mt < 4; mt++) {
        #pragma unroll
        for (int nt = 0; nt < 4; nt++) {
            int r  = row0 + warpM + mt * 16 + gid;
            int cc = (warpNg + nt) * 8 + tig * 2;
            if (r < n)
                *(__half2*)(g_Hh + (size_t)r * HH + cc) =
                    __floats2half2_rn(acc[mt][nt][0], acc[mt][nt][1]);
            if (r + 8 < n)
                *(__half2*)(g_Hh + (size_t)(r + 8) * HH + cc) =
                    __floats2half2_rn(acc[mt][nt][2], acc[mt][nt][3]);
        }
    }
}

// ---------------- fused aggregate (fp16 gathers, fp16 X out) ----------------
template<int RELU, int RES>
__global__ __launch_bounds__(256)
void agg_k(const float* __restrict__ b, const float* __restrict__ rw,
           int out_sel, int n) {
    __half* __restrict__ Xout = out_sel ? g_X2 : g_X1;
    const __half* __restrict__ Xres = out_sel ? g_X1 : g_X2;
    const __half* __restrict__ H = g_Hh;

    int node = blockIdx.x * (blockDim.x >> 5) + (threadIdx.x >> 5);
    if (node >= n) return;
    int lane = threadIdx.x & 31;
    int beg = __ldg(&g_off[node]);
    int end = __ldg(&g_off[node + 1]);

    float ax = 0.f, ay = 0.f, az = 0.f, aw = 0.f;
    int e = beg;
    for (; e + 1 < end; e += 2) {
        int2 e0 = __ldg(&g_edge[e]);
        int2 e1 = __ldg(&g_edge[e + 1]);
        float w0 = __int_as_float(e0.y);
        float w1 = __int_as_float(e1.y);
        uint2 r0 = *(const uint2*)(H + (size_t)e0.x * HH + lane * 4);
        uint2 r1 = *(const uint2*)(H + (size_t)e1.x * HH + lane * 4);
        float2 f00 = __half22float2(*(__half2*)&r0.x);
        float2 f01 = __half22float2(*(__half2*)&r0.y);
        float2 f10 = __half22float2(*(__half2*)&r1.x);
        float2 f11 = __half22float2(*(__half2*)&r1.y);
        ax += w0 * f00.x + w1 * f10.x;
        ay += w0 * f00.y + w1 * f10.y;
        az += w0 * f01.x + w1 * f11.x;
        aw += w0 * f01.y + w1 * f11.y;
    }
    if (e < end) {
        int2 e0 = __ldg(&g_edge[e]);
        float w0 = __int_as_float(e0.y);
        uint2 r0 = *(const uint2*)(H + (size_t)e0.x * HH + lane * 4);
        float2 f00 = __half22float2(*(__half2*)&r0.x);
        float2 f01 = __half22float2(*(__half2*)&r0.y);
        ax += w0 * f00.x; ay += w0 * f00.y; az += w0 * f01.x; aw += w0 * f01.y;
    }

    float dv = __ldg(&g_dinv[node]);
    float sn = dv * dv;
    uint2 rs = *(const uint2*)(H + (size_t)node * HH + lane * 4);
    float2 s0 = __half22float2(*(__half2*)&rs.x);
    float2 s1 = __half22float2(*(__half2*)&rs.y);
    float4 bb = *(const float4*)(b + lane * 4);
    float vx = ax + sn * s0.x + bb.x;
    float vy = ay + sn * s0.y + bb.y;
    float vz = az + sn * s1.x + bb.z;
    float vw = aw + sn * s1.y + bb.w;
    if (RELU) {
        vx = fmaxf(vx, 0.f); vy = fmaxf(vy, 0.f);
        vz = fmaxf(vz, 0.f); vw = fmaxf(vw, 0.f);
    }
    if (RES) {
        float w = *rw;
        uint2 rr = *(const uint2*)(Xres + (size_t)node * HH + lane * 4);
        float2 x0 = __half22float2(*(__half2*)&rr.x);
        float2 x1 = __half22float2(*(__half2*)&rr.y);
        vx += w * x0.x; vy += w * x0.y; vz += w * x1.x; vw += w * x1.y;
    }
    uint2 o;
    *(__half2*)&o.x = __floats2half2_rn(vx, vy);
    *(__half2*)&o.y = __floats2half2_rn(vz, vw);
    *(uint2*)(Xout + (size_t)node * HH + lane * 4) = o;
}

// ---------------- head: out[n,40] = g_X2[n,128] @ mlp_W[128,40] + b ----------------
__global__ void head_k(const float* __restrict__ W, const float* __restrict__ b,
                       float* __restrict__ out, int n) {
    int idx = blockIdx.x * blockDim.x + threadIdx.x;
    if (idx >= n * CC) return;
    int node = idx / CC;
    int c    = idx % CC;
    const __half* xr = g_X2 + (size_t)node * HH;
    float a0 = 0.f, a1 = 0.f, a2 = 0.f, a3 = 0.f;
    #pragma unroll
    for (int k = 0; k < HH; k += 4) {
        uint2 p = *(const uint2*)(xr + k);
        float2 f0 = __half22float2(*(__half2*)&p.x);
        float2 f1 = __half22float2(*(__half2*)&p.y);
        a0 += f0.x * __ldg(W + (k + 0) * CC + c);
        a1 += f0.y * __ldg(W + (k + 1) * CC + c);
        a2 += f1.x * __ldg(W + (k + 2) * CC + c);
        a3 += f1.y * __ldg(W + (k + 3) * CC + c);
    }
    out[idx] = (a0 + a1) + (a2 + a3) + b[c];
}

// ---------------- launch ----------------
extern "C" void kernel_launch(void* const* d_in, const int* in_sizes, int n_in,
                              void* d_out, int out_size) {
    const float* X    = (const float*)d_in[0];
    const void*  ei   = d_in[1];
    const float* Ws   = (const float*)d_in[2];
    const float* bs   = (const float*)d_in[3];
    const float* mlpW = (const float*)d_in[4];
    const float* mlpb = (const float*)d_in[5];
    const float* rw   = (const float*)d_in[6];
    float* out = (float*)d_out;

    int n = in_sizes[0] / HH;
    int E = in_sizes[1] / 2;

    const int T = 256;
    int B = (n + SCAN_CHUNK - 1) / SCAN_CHUNK;

    init_k <<<(n + T - 1) / T, T>>>(ei, E, n);
    wfrag_k<<<(4 * 8 * 16 * 32 + T - 1) / T, T>>>(Ws);
    hist_k <<<(E + T - 1) / T, T>>>(ei, E);
    bsum_k <<<B, 256>>>(n);
    bscan_k<<<1, 32>>>(B);
    offs_k <<<B, 256>>>(n, B);
    bucket_k<<<(E + T - 1) / T, T>>>(ei, E);

    int gblocks = (n + 127) / 128;
    int ablocks = (n + 7) / 8;

    gemm_bf16_k<<<gblocks, T>>>(X, 0, 0, n);
    agg_k<1, 0><<<ablocks, T>>>(bs + 0 * HH, rw, 0, n);
    gemm_bf16_k<<<gblocks, T>>>(X, 1, 1, n);
    agg_k<1, 1><<<ablocks, T>>>(bs + 1 * HH, rw, 1, n);
    gemm_bf16_k<<<gblocks, T>>>(X, 2, 2, n);
    agg_k<1, 1><<<ablocks, T>>>(bs + 2 * HH, rw, 0, n);
    gemm_bf16_k<<<gblocks, T>>>(X, 3, 1, n);
    agg_k<0, 0><<<ablocks, T>>>(bs + 3 * HH, rw, 1, n);

    head_k<<<(n * CC + T - 1) / T, T>>>(mlpW, mlpb, out, n);
}